// round 12
// baseline (speedup 1.0000x reference)
#include <cuda_runtime.h>
#include <cuda_fp16.h>
#include <cstdint>
#include <math.h>

// Problem constants (fixed for this dataset)
#define MAXN 50000
#define MAXE 800000
#define MAXG 512
#define HID  256

// ---------------------------------------------------------------------------
// Scratch (__device__ globals: allocation-free per harness rules)
__device__ __half g_A[(size_t)MAXN * HID];            // agg output, fp16
__device__ __half g_H[(size_t)MAXN * HID];            // hidden state, fp16
__device__ __half g_x16[(size_t)MAXN * 128];          // fp16 copy of input x
__device__ float g_dis[MAXN];
__device__ int   g_counts[MAXN];
__device__ int   g_offs[MAXN + 1];
__device__ int   g_wptr[MAXN];
__device__ int   g_csr[MAXE];
__device__ float g_sums[MAXG * HID];
__device__ int   g_gcnt[MAXG];
__device__ int   g_bsum[64];
// transposed weights: [N=256 rows][K cols], K-major fp16
__device__ __half g_W1t[256 * 128];
__device__ __half g_W2t[256 * 256];
__device__ __half g_W3t[256 * 256];

// ---------------------------------------------------------------------------
// base-ISA tensor helpers (mma.sync / ldmatrix / cp.async)
__device__ __forceinline__ void ldsm_x4(uint32_t& r0, uint32_t& r1, uint32_t& r2, uint32_t& r3,
                                        uint32_t addr) {
    asm volatile("ldmatrix.sync.aligned.m8n8.x4.shared.b16 {%0,%1,%2,%3}, [%4];"
                 : "=r"(r0), "=r"(r1), "=r"(r2), "=r"(r3) : "r"(addr));
}
__device__ __forceinline__ void mma_fp16(float* c, const uint32_t* a, uint32_t b0, uint32_t b1) {
    asm volatile("mma.sync.aligned.m16n8k16.row.col.f32.f16.f16.f32 "
                 "{%0,%1,%2,%3}, {%4,%5,%6,%7}, {%8,%9}, {%0,%1,%2,%3};"
                 : "+f"(c[0]), "+f"(c[1]), "+f"(c[2]), "+f"(c[3])
                 : "r"(a[0]), "r"(a[1]), "r"(a[2]), "r"(a[3]), "r"(b0), "r"(b1));
}
__device__ __forceinline__ void cp_async16(uint32_t smem_addr, const void* gptr, uint32_t src_sz) {
    asm volatile("cp.async.cg.shared.global [%0], [%1], 16, %2;"
                 :: "r"(smem_addr), "l"(gptr), "r"(src_sz) : "memory");
}
#define CP_COMMIT() asm volatile("cp.async.commit_group;" ::: "memory")
#define CP_WAIT(n)  asm volatile("cp.async.wait_group %0;" :: "n"(n) : "memory")
__device__ __forceinline__ uint32_t smem_u32(const void* p) {
    uint32_t a;
    asm("{ .reg .u64 t; cvta.to.shared.u64 t, %1; cvt.u32.u64 %0, t; }" : "=r"(a) : "l"(p));
    return a;
}

// ---------------------------------------------------------------------------
// 0. zero-init
__global__ void init_kernel(int n_nodes, int n_graphs) {
    int i = blockIdx.x * blockDim.x + threadIdx.x;
    int total = n_nodes + n_graphs + n_graphs * HID;
    for (; i < total; i += gridDim.x * blockDim.x) {
        if (i < n_nodes) g_counts[i] = 0;
        else if (i < n_nodes + n_graphs) g_gcnt[i - n_nodes] = 0;
        else g_sums[i - n_nodes - n_graphs] = 0.0f;
    }
}
// 1. in-degree counts + per-graph node counts (merged)
__global__ void count_gcnt(const int* __restrict__ ei, const int* __restrict__ batch,
                           int E, int N) {
    int i = blockIdx.x * blockDim.x + threadIdx.x;
    if (i < E) atomicAdd(&g_counts[ei[E + i]], 1);
    else if (i < E + N) atomicAdd(&g_gcnt[batch[i - E]], 1);
}
// 1b. convert input x to fp16
__global__ void xhalf_kernel(const float* __restrict__ x, __half* __restrict__ o, int total4) {
    int i = blockIdx.x * blockDim.x + threadIdx.x;
    if (i < total4) {
        float4 f = ((const float4*)x)[i];
        __half2 a = __floats2half2_rn(f.x, f.y);
        __half2 b = __floats2half2_rn(f.z, f.w);
        uint2 u; u.x = *(uint32_t*)&a; u.y = *(uint32_t*)&b;
        ((uint2*)o)[i] = u;
    }
}
// 2a. per-block reduce -> g_bsum
__global__ void scan_p1(int n) {
    int i = blockIdx.x * 1024 + threadIdx.x;
    int v = (i < n) ? g_counts[i] : 0;
    __shared__ int sw[32];
    int lane = threadIdx.x & 31, wid = threadIdx.x >> 5;
    int s = v;
    #pragma unroll
    for (int o = 16; o > 0; o >>= 1) s += __shfl_down_sync(0xffffffffu, s, o);
    if (lane == 0) sw[wid] = s;
    __syncthreads();
    if (wid == 0) {
        int t = sw[lane];
        #pragma unroll
        for (int o = 16; o > 0; o >>= 1) t += __shfl_down_sync(0xffffffffu, t, o);
        if (lane == 0) g_bsum[blockIdx.x] = t;
    }
}
// 2b. one block scans block sums
__global__ void scan_p2(int nb, int n) {
    int lane = threadIdx.x;  // 64 threads
    __shared__ int sm[64];
    int v = (lane < nb) ? g_bsum[lane] : 0;
    sm[lane] = v;
    __syncthreads();
    #pragma unroll
    for (int d = 1; d < 64; d <<= 1) {
        int t = (lane >= d) ? sm[lane - d] : 0;
        __syncthreads();
        sm[lane] += t;
        __syncthreads();
    }
    if (lane < nb) g_bsum[lane] = sm[lane] - v;
    if (lane == nb - 1) g_offs[n] = sm[lane];
}
// 2c. per-block inclusive scan + base -> offs/wptr/dis
__global__ void scan_p3(int n) {
    int base = g_bsum[blockIdx.x];
    int i = blockIdx.x * 1024 + threadIdx.x;
    int v = (i < n) ? g_counts[i] : 0;
    __shared__ int sw[32];
    int lane = threadIdx.x & 31, wid = threadIdx.x >> 5;
    int inc = v;
    #pragma unroll
    for (int o = 1; o < 32; o <<= 1) {
        int t = __shfl_up_sync(0xffffffffu, inc, o);
        if (lane >= o) inc += t;
    }
    if (lane == 31) sw[wid] = inc;
    __syncthreads();
    if (wid == 0) {
        int t = sw[lane];
        #pragma unroll
        for (int o = 1; o < 32; o <<= 1) {
            int u = __shfl_up_sync(0xffffffffu, t, o);
            if (lane >= o) t += u;
        }
        sw[lane] = t;
    }
    __syncthreads();
    int excl = base + inc - v + (wid > 0 ? sw[wid - 1] : 0);
    if (i < n) {
        g_offs[i] = excl;
        g_wptr[i] = excl;
        g_dis[i]  = rsqrtf(1.0f + (float)v);
    }
}
// 3. fill CSR
__global__ void fill_kernel(const int* __restrict__ ei, int E) {
    int e = blockIdx.x * blockDim.x + threadIdx.x;
    if (e < E) {
        int s = ei[e], d = ei[E + e];
        g_csr[atomicAdd(&g_wptr[d], 1)] = s;
    }
}

// ---------------------------------------------------------------------------
// 4. warp-per-node aggregation on fp16 rows -> fp16 out. F in {128, 256}.
template <int F>
__global__ void agg_f16(const __half* __restrict__ h, __half* __restrict__ oh, int N) {
    constexpr int HPL = F / 32;
    constexpr int W2L = HPL / 2;
    int node = blockIdx.x * (blockDim.x >> 5) + (threadIdx.x >> 5);
    int lane = threadIdx.x & 31;
    if (node >= N) return;

    float di = g_dis[node];
    float acc[HPL];
    {
        uint32_t v[W2L];
        if constexpr (F == 128) {
            uint2 u = ((const uint2*)(h + (size_t)node * F))[lane];
            v[0] = u.x; v[1] = u.y;
        } else {
            uint4 u = ((const uint4*)(h + (size_t)node * F))[lane];
            v[0] = u.x; v[1] = u.y; v[2] = u.z; v[3] = u.w;
        }
        #pragma unroll
        for (int q = 0; q < W2L; q++) {
            float2 f = __half22float2(*(__half2*)&v[q]);
            acc[2*q]   = di * f.x;
            acc[2*q+1] = di * f.y;
        }
    }
    int e0 = g_offs[node], e1 = g_offs[node + 1];
    for (int base = e0; base < e1; base += 32) {
        int e = base + lane;
        int s = 0; float w = 0.0f;
        if (e < e1) { s = g_csr[e]; w = g_dis[s]; }
        int cnt = min(32, e1 - base);
        #pragma unroll 4
        for (int j = 0; j < cnt; j++) {
            int   sj = __shfl_sync(0xffffffffu, s, j);
            float wj = __shfl_sync(0xffffffffu, w, j);
            uint32_t v[W2L];
            if constexpr (F == 128) {
                uint2 u = ((const uint2*)(h + (size_t)sj * F))[lane];
                v[0] = u.x; v[1] = u.y;
            } else {
                uint4 u = ((const uint4*)(h + (size_t)sj * F))[lane];
                v[0] = u.x; v[1] = u.y; v[2] = u.z; v[3] = u.w;
            }
            #pragma unroll
            for (int q = 0; q < W2L; q++) {
                float2 f = __half22float2(*(__half2*)&v[q]);
                acc[2*q]   += wj * f.x;
                acc[2*q+1] += wj * f.y;
            }
        }
    }
    uint32_t o[W2L];
    #pragma unroll
    for (int q = 0; q < W2L; q++) {
        __half2 hv = __floats2half2_rn(di * acc[2*q], di * acc[2*q+1]);
        o[q] = *(uint32_t*)&hv;
    }
    if constexpr (F == 128) {
        uint2 u; u.x = o[0]; u.y = o[1];
        ((uint2*)(oh + (size_t)node * F))[lane] = u;
    } else {
        uint4 u; u.x = o[0]; u.y = o[1]; u.z = o[2]; u.w = o[3];
        ((uint4*)(oh + (size_t)node * F))[lane] = u;
    }
}

// 5. all three weight transposes in one launch
__global__ void wtrans_all(const float* __restrict__ W1, const float* __restrict__ W2,
                           const float* __restrict__ W3, int K1) {
    int i = blockIdx.x * blockDim.x + threadIdx.x;
    int sz1 = K1 * 256, sz23 = 256 * 256;
    const float* W; __half* Wt; int idx, K;
    if (i < sz1)               { W = W1; Wt = g_W1t; idx = i;              K = K1;  }
    else if (i < sz1 + sz23)   { W = W2; Wt = g_W2t; idx = i - sz1;        K = 256; }
    else if (i < sz1 + 2*sz23) { W = W3; Wt = g_W3t; idx = i - sz1 - sz23; K = 256; }
    else return;
    int k = idx / 256, n = idx % 256;
    Wt[n * K + k] = __float2half_rn(W[idx]);
}

// ---------------------------------------------------------------------------
// 6. persistent pure-fp16 tensor-core GEMM, 3-stage cp.async pipeline.
//    C = relu( A @ B^T + bias ), fp32 accumulate. Grid = 296 CTAs, each loops
//    over its 128x128 tiles. Stage covers k=32 (two k16 slabs), 3 stages.
#define PITCH_B 32
#define TILE_B  4096
#define SLAB_B  8192             // one k16 slab: A, B tiles
#define STAGE_B (2 * SLAB_B)     // 16 KB per stage (k=32)

template <bool POOL>
__global__ void __launch_bounds__(256, 2)
gemm_tc(const __half* __restrict__ A, const __half* __restrict__ B,
        const float* __restrict__ bias, __half* __restrict__ C,
        const int* __restrict__ batch, int M, int K) {
    extern __shared__ __align__(1024) char smem[];
    uint32_t sbase = smem_u32(smem);

    int tid = threadIdx.x;
    int wid = tid >> 5, lane = tid & 31;
    int wm = wid >> 2, wn = wid & 3;
    int r = lane & 15, sel = lane >> 4;
    int qr = lane >> 2, qc = lane & 3;

    int ntm = (M + 127) >> 7;
    int tiles = ntm * 2;
    int npair = K >> 5;

    for (int tile = blockIdx.x; tile < tiles; tile += gridDim.x) {
        int m0 = (tile >> 1) * 128;
        int n0 = (tile & 1) * 128;

        float acc[4][4][4];
        #pragma unroll
        for (int i = 0; i < 4; i++)
            #pragma unroll
            for (int j = 0; j < 4; j++)
                #pragma unroll
                for (int q = 0; q < 4; q++) acc[i][j][q] = 0.0f;

        auto load_slab = [&](uint32_t sb, int k0) {
            #pragma unroll
            for (int i = 0; i < 2; i++) {
                int c = tid + i * 256;
                int tl = c >> 8, t = c & 255;
                int row = t >> 1, half = t & 1;
                uint32_t dst = sb + tl * TILE_B + row * PITCH_B +
                               ((half ^ ((row >> 2) & 1)) << 4);
                const __half* src;
                uint32_t sz = 16;
                if (tl == 0) {
                    int gr = m0 + row;
                    int cr = gr < M ? gr : (M - 1);
                    src = A + (size_t)cr * K + k0 + half * 8;
                    if (gr >= M) sz = 0;
                } else {
                    src = B + (size_t)(n0 + row) * K + k0 + half * 8;
                }
                cp_async16(dst, src, sz);
            }
        };
        auto load_pair = [&](int stage, int p) {
            uint32_t sb = sbase + stage * STAGE_B;
            load_slab(sb,          p * 32);
            load_slab(sb + SLAB_B, p * 32 + 16);
            CP_COMMIT();
        };
        auto compute_slab = [&](uint32_t sb) {
            uint32_t sA = sb, sB = sb + TILE_B;
            uint32_t af[4][4];
            #pragma unroll
            for (int mi = 0; mi < 4; mi++) {
                int rowA = wm * 64 + mi * 16 + r;
                uint32_t off = rowA * PITCH_B + ((sel ^ ((rowA >> 2) & 1)) << 4);
                ldsm_x4(af[mi][0], af[mi][1], af[mi][2], af[mi][3], sA + off);
            }
            uint32_t bf[2][4];
            #pragma unroll
            for (int nj = 0; nj < 2; nj++) {
                int rowB = wn * 32 + nj * 16 + r;
                uint32_t off = rowB * PITCH_B + ((sel ^ ((rowB >> 2) & 1)) << 4);
                ldsm_x4(bf[nj][0], bf[nj][1], bf[nj][2], bf[nj][3], sB + off);
            }
            #pragma unroll
            for (int mi = 0; mi < 4; mi++) {
                #pragma unroll
                for (int nn = 0; nn < 4; nn++) {
                    int nj = nn >> 1, hi8 = nn & 1;
                    mma_fp16(acc[mi][nn], af[mi], bf[nj][hi8], bf[nj][hi8 + 2]);
                }
            }
        };

        // 3-stage pipeline: prefetch 2, keep up to 2 groups in flight
        load_pair(0, 0);
        if (npair > 1) load_pair(1, 1);

        for (int p = 0; p < npair; p++) {
            if (p + 2 < npair) {
                load_pair((p + 2) % 3, p + 2);
                CP_WAIT(2);
            } else if (p + 1 < npair) {
                CP_WAIT(1);
            } else {
                CP_WAIT(0);
            }
            __syncthreads();
            uint32_t sb = sbase + (p % 3) * STAGE_B;
            compute_slab(sb);
            compute_slab(sb + SLAB_B);
            __syncthreads();
        }

        // epilogue
        #pragma unroll
        for (int nn = 0; nn < 4; nn++) {
            int col = n0 + wn * 32 + (nn >> 1) * 16 + (nn & 1) * 8 + qc * 2;
            float bz0 = __ldg(&bias[col]), bz1 = __ldg(&bias[col + 1]);
            #pragma unroll
            for (int mi = 0; mi < 4; mi++) {
                int row0 = m0 + wm * 64 + mi * 16 + qr;
                if (row0 < M) {
                    float v0 = fmaxf(acc[mi][nn][0] + bz0, 0.f);
                    float v1 = fmaxf(acc[mi][nn][1] + bz1, 0.f);
                    if (POOL) {
                        int g = __ldg(&batch[row0]);
                        atomicAdd(&g_sums[g * HID + col],     v0);
                        atomicAdd(&g_sums[g * HID + col + 1], v1);
                    } else {
                        __half2 hv = __floats2half2_rn(v0, v1);
                        *(__half2*)(C + (size_t)row0 * 256 + col) = hv;
                    }
                }
                int row1 = row0 + 8;
                if (row1 < M) {
                    float v2 = fmaxf(acc[mi][nn][2] + bz0, 0.f);
                    float v3 = fmaxf(acc[mi][nn][3] + bz1, 0.f);
                    if (POOL) {
                        int g = __ldg(&batch[row1]);
                        atomicAdd(&g_sums[g * HID + col],     v2);
                        atomicAdd(&g_sums[g * HID + col + 1], v3);
                    } else {
                        __half2 hv = __floats2half2_rn(v2, v3);
                        *(__half2*)(C + (size_t)row1 * 256 + col) = hv;
                    }
                }
            }
        }
    }
}

// ---------------------------------------------------------------------------
// 7. head: mean, concat, fc1(relu), fc2 -> out[G,16]
__global__ void head_kernel(const float* __restrict__ molwt, const float* __restrict__ nrings,
                            const float* __restrict__ fcW1, const float* __restrict__ fcb1,
                            const float* __restrict__ fcW2, const float* __restrict__ fcb2,
                            float* __restrict__ out) {
    int g = blockIdx.x;
    __shared__ float hg[258];
    __shared__ float h1[196];
    int t = threadIdx.x;  // 256
    float c = fmaxf((float)g_gcnt[g], 1.0f);
    hg[t] = g_sums[g * HID + t] / c;
    if (t == 0) { hg[256] = molwt[g]; hg[257] = nrings[g]; }
    __syncthreads();
    if (t < 196) {
        float a = fcb1[t];
        #pragma unroll 4
        for (int k = 0; k < 258; k++) a += hg[k] * fcW1[k * 196 + t];
        h1[t] = fmaxf(a, 0.0f);
    }
    __syncthreads();
    if (t < 16) {
        float a = fcb2[t];
        #pragma unroll 4
        for (int k = 0; k < 196; k++) a += h1[k] * fcW2[k * 16 + t];
        out[g * 16 + t] = a;
    }
}

// ---------------------------------------------------------------------------
extern "C" void kernel_launch(void* const* d_in, const int* in_sizes, int n_in,
                              void* d_out, int out_size) {
    const float* x      = (const float*)d_in[0];
    const int*   ei     = (const int*)  d_in[1];
    const int*   batch  = (const int*)  d_in[2];
    const float* molwt  = (const float*)d_in[3];
    const float* nrings = (const float*)d_in[4];
    const float* W1 = (const float*)d_in[5];
    const float* b1 = (const float*)d_in[6];
    const float* W2 = (const float*)d_in[7];
    const float* b2 = (const float*)d_in[8];
    const float* W3 = (const float*)d_in[9];
    const float* b3 = (const float*)d_in[10];
    const float* fcW1 = (const float*)d_in[11];
    const float* fcb1 = (const float*)d_in[12];
    const float* fcW2 = (const float*)d_in[13];
    const float* fcb2 = (const float*)d_in[14];

    const int N = in_sizes[2];
    const int E = in_sizes[1] / 2;
    const int G = in_sizes[3];
    const int F_IN = in_sizes[0] / N;   // 128

    __half *A, *H, *X16, *W1t, *W2t, *W3t;
    cudaGetSymbolAddress((void**)&A, g_A);
    cudaGetSymbolAddress((void**)&H, g_H);
    cudaGetSymbolAddress((void**)&X16, g_x16);
    cudaGetSymbolAddress((void**)&W1t, g_W1t);
    cudaGetSymbolAddress((void**)&W2t, g_W2t);
    cudaGetSymbolAddress((void**)&W3t, g_W3t);

    const int GEMM_SMEM = 3 * STAGE_B;   // 49152
    cudaFuncSetAttribute(gemm_tc<false>, cudaFuncAttributeMaxDynamicSharedMemorySize, GEMM_SMEM);
    cudaFuncSetAttribute(gemm_tc<true >, cudaFuncAttributeMaxDynamicSharedMemorySize, GEMM_SMEM);

    int nb = (N + 1023) / 1024;
    int gemmgrid = 296;                  // 2 CTAs/SM persistent
    int aggblocks = (N + 7) / 8;         // 8 warps / block

    // setup
    init_kernel<<<256, 256>>>(N, G);
    count_gcnt<<<(E + N + 255) / 256, 256>>>(ei, batch, E, N);
    xhalf_kernel<<<(N * F_IN / 4 + 255) / 256, 256>>>(x, X16, N * F_IN / 4);
    scan_p1<<<nb, 1024>>>(N);
    scan_p2<<<1, 64>>>(nb, N);
    scan_p3<<<nb, 1024>>>(N);
    fill_kernel<<<(E + 255) / 256, 256>>>(ei, E);
    int wtot = F_IN * 256 + 2 * 256 * 256;
    wtrans_all<<<(wtot + 255) / 256, 256>>>(W1, W2, W3, F_IN);

    // layer 1
    agg_f16<128><<<aggblocks, 256>>>(X16, A, N);
    gemm_tc<false><<<gemmgrid, 256, GEMM_SMEM>>>(A, W1t, b1, H, nullptr, N, F_IN);
    // layer 2
    agg_f16<256><<<aggblocks, 256>>>(H, A, N);
    gemm_tc<false><<<gemmgrid, 256, GEMM_SMEM>>>(A, W2t, b2, H, nullptr, N, HID);
    // layer 3 (pooling fused into epilogue)
    agg_f16<256><<<aggblocks, 256>>>(H, A, N);
    gemm_tc<true><<<gemmgrid, 256, GEMM_SMEM>>>(A, W3t, b3, nullptr, batch, N, HID);

    // head
    head_kernel<<<G, 256>>>(molwt, nrings, fcW1, fcb1, fcW2, fcb2, (float*)d_out);
}